// round 2
// baseline (speedup 1.0000x reference)
#include <cuda_runtime.h>
#include <math.h>

#define BATCH 4
#define NG 1024
#define NC 1024
#define NQ 256
#define NF 512
#define NH 8
#define HD 64
#define NL 2
#define ALPHAF 0.2f
#define NEGV -9e15f

// ---------------- scratch (device globals; no allocation allowed) ----------------
__device__ float g_Ga[BATCH*NG*NF];   // gloss after layer 0
__device__ float g_Ca[BATCH*NC*NF];   // clip after layer 0
__device__ float g_Qa[BATCH*NQ*NF];   // question after layer 0
__device__ float g_G1[BATCH*NG*NF];   // gloss_1 within a layer
__device__ float g_AGG[BATCH*NG*NF];  // gloss_same / *_agg scratch
__device__ float g_Pq[BATCH*NG*NF];   // query projection
__device__ float g_Pk[BATCH*NG*NF];   // key projection
__device__ float g_T1[BATCH*NG*NF];   // fusion tmp new_a
__device__ float g_T2[BATCH*NG*NF];   // fusion tmp gate pre-sigmoid
__device__ float g_Wt[NF*NF];         // transposed attention W
__device__ float g_s1[BATCH*NH*NG];
__device__ float g_s2[BATCH*NH*NG];
__device__ float g_cmax[BATCH*NH*NG];
__device__ float g_csum[BATCH*NH*NG];

// ---------------- generic fp32 GEMM: C (+)= A[M,K] @ B[K,N] ----------------
// 64x64 tile, BK=16, 256 threads, 4x4 per thread. Requires M%64==0, N%64==0, K%16==0.
template<int ACC>
__global__ __launch_bounds__(256) void gemm_nn(const float* __restrict__ A,
                                               const float* __restrict__ B,
                                               float* __restrict__ C,
                                               int M, int N, int K) {
    __shared__ float As[16][64];
    __shared__ float Bs[16][64];
    const int tid = threadIdx.x;
    const int tx = tid & 15, ty = tid >> 4;
    const int row0 = blockIdx.y * 64, col0 = blockIdx.x * 64;
    const int ra = tid >> 2, ka = (tid & 3) << 2;       // A tile: 64 rows x 16 k
    const int kb = tid >> 4, cb = (tid & 15) << 2;      // B tile: 16 k x 64 cols
    float acc[4][4] = {};
    for (int k0 = 0; k0 < K; k0 += 16) {
        float4 av = *(const float4*)(A + (size_t)(row0 + ra) * K + k0 + ka);
        As[ka + 0][ra] = av.x; As[ka + 1][ra] = av.y;
        As[ka + 2][ra] = av.z; As[ka + 3][ra] = av.w;
        float4 bv = *(const float4*)(B + (size_t)(k0 + kb) * N + col0 + cb);
        Bs[kb][cb + 0] = bv.x; Bs[kb][cb + 1] = bv.y;
        Bs[kb][cb + 2] = bv.z; Bs[kb][cb + 3] = bv.w;
        __syncthreads();
#pragma unroll
        for (int k = 0; k < 16; k++) {
            float a_[4], b_[4];
#pragma unroll
            for (int i = 0; i < 4; i++) a_[i] = As[k][(ty << 2) + i];
#pragma unroll
            for (int j = 0; j < 4; j++) b_[j] = Bs[k][(tx << 2) + j];
#pragma unroll
            for (int i = 0; i < 4; i++)
#pragma unroll
                for (int j = 0; j < 4; j++) acc[i][j] += a_[i] * b_[j];
        }
        __syncthreads();
    }
#pragma unroll
    for (int i = 0; i < 4; i++) {
        int r = row0 + (ty << 2) + i;
#pragma unroll
        for (int j = 0; j < 4; j++) {
            int c = col0 + (tx << 2) + j;
            if (ACC) C[(size_t)r * N + c] += acc[i][j];
            else     C[(size_t)r * N + c]  = acc[i][j];
        }
    }
}

// ---------------- gloss_same: C[b,m,f] = sum_n adj[b,n,m] * X[b,n,f] ----------------
__global__ __launch_bounds__(256) void gemm_adjT(const int* __restrict__ adj,
                                                 const float* __restrict__ X,
                                                 float* __restrict__ C,
                                                 int N, int Mo, int F_) {
    const int b = blockIdx.z;
    const int* A = adj + (size_t)b * N * Mo;
    const float* Xb = X + (size_t)b * N * F_;
    float* Cb = C + (size_t)b * Mo * F_;
    __shared__ float As[16][64];   // [n][m]
    __shared__ float Bs[16][64];   // [n][f]
    const int tid = threadIdx.x;
    const int tx = tid & 15, ty = tid >> 4;
    const int m0 = blockIdx.y * 64, f0 = blockIdx.x * 64;
    const int na = tid >> 4, ca = (tid & 15) << 2;
    float acc[4][4] = {};
    for (int n0 = 0; n0 < N; n0 += 16) {
        int4 av = *(const int4*)(A + (size_t)(n0 + na) * Mo + m0 + ca);
        As[na][ca + 0] = (float)av.x; As[na][ca + 1] = (float)av.y;
        As[na][ca + 2] = (float)av.z; As[na][ca + 3] = (float)av.w;
        float4 bv = *(const float4*)(Xb + (size_t)(n0 + na) * F_ + f0 + ca);
        Bs[na][ca + 0] = bv.x; Bs[na][ca + 1] = bv.y;
        Bs[na][ca + 2] = bv.z; Bs[na][ca + 3] = bv.w;
        __syncthreads();
#pragma unroll
        for (int k = 0; k < 16; k++) {
            float a_[4], b_[4];
#pragma unroll
            for (int i = 0; i < 4; i++) a_[i] = As[k][(ty << 2) + i];
#pragma unroll
            for (int j = 0; j < 4; j++) b_[j] = Bs[k][(tx << 2) + j];
#pragma unroll
            for (int i = 0; i < 4; i++)
#pragma unroll
                for (int j = 0; j < 4; j++) acc[i][j] += a_[i] * b_[j];
        }
        __syncthreads();
    }
#pragma unroll
    for (int i = 0; i < 4; i++) {
        int m = m0 + (ty << 2) + i;
#pragma unroll
        for (int j = 0; j < 4; j++)
            Cb[(size_t)m * F_ + f0 + (tx << 2) + j] = acc[i][j];
    }
}

// ---------------- W [H,F,D] -> Wt [F, H*D] ----------------
__global__ void transposeW(const float* __restrict__ W, float* __restrict__ Wt) {
    int i = blockIdx.x * blockDim.x + threadIdx.x;   // i enumerates (f,h,d)
    if (i >= NF * NH * HD) return;
    int d = i & (HD - 1);
    int h = (i >> 6) & (NH - 1);
    int f = i >> 9;
    Wt[i] = W[((size_t)h * NF + f) * HD + d];
}

// ---------------- s[b,h,n] = dot(P[b,n,h*64:...], a[h,:]) ----------------
__global__ void scores_k(const float* __restrict__ P, const float* __restrict__ a,
                         float* __restrict__ s, int Ntok) {
    int i = blockIdx.x * blockDim.x + threadIdx.x;
    if (i >= BATCH * NH * Ntok) return;
    int n = i % Ntok;
    int h = (i / Ntok) % NH;
    int b = i / (Ntok * NH);
    const float* row = P + ((size_t)(b * Ntok + n)) * NF + h * HD;
    const float* av = a + h * HD;
    float acc = 0.f;
#pragma unroll
    for (int d = 0; d < HD; d++) acc += row[d] * av[d];
    s[i] = acc;   // i == (b*NH + h)*Ntok + n
}

// ---------------- per-column (over n) online max/sum of masked lrelu scores ----------------
__global__ __launch_bounds__(256) void colstats_k(const int* __restrict__ adj, int adjT,
                                                  const float* __restrict__ s1,
                                                  const float* __restrict__ s2,
                                                  float* __restrict__ cmax,
                                                  float* __restrict__ csum,
                                                  int N, int M) {
    const int m = blockIdx.x, b = blockIdx.y;
    float mx[NH], sm[NH], s2v[NH];
#pragma unroll
    for (int h = 0; h < NH; h++) {
        mx[h] = -INFINITY; sm[h] = 0.f;
        s2v[h] = s2[((size_t)(b * NH + h)) * M + m];
    }
    for (int n = threadIdx.x; n < N; n += 256) {
        int a = adjT ? adj[((size_t)(b * M + m)) * N + n]
                     : adj[((size_t)(b * N + n)) * M + m];
#pragma unroll
        for (int h = 0; h < NH; h++) {
            float e;
            if (a > 0) { float x = s1[((size_t)(b * NH + h)) * N + n] + s2v[h];
                         e = x > 0.f ? x : ALPHAF * x; }
            else e = NEGV;
            if (e > mx[h]) { sm[h] = sm[h] * expf(mx[h] - e) + 1.f; mx[h] = e; }
            else sm[h] += expf(e - mx[h]);
        }
    }
    __shared__ float shm[256], shs[256];
    for (int h = 0; h < NH; h++) {
        shm[threadIdx.x] = mx[h]; shs[threadIdx.x] = sm[h];
        __syncthreads();
        for (int st = 128; st > 0; st >>= 1) {
            if (threadIdx.x < st) {
                float m1 = shm[threadIdx.x], s1x = shs[threadIdx.x];
                float m2 = shm[threadIdx.x + st], s2x = shs[threadIdx.x + st];
                float Mx = fmaxf(m1, m2);
                float S = (Mx == -INFINITY) ? 0.f
                        : s1x * expf(m1 - Mx) + s2x * expf(m2 - Mx);
                shm[threadIdx.x] = Mx; shs[threadIdx.x] = S;
            }
            __syncthreads();
        }
        if (threadIdx.x == 0) {
            cmax[((size_t)(b * NH + h)) * M + m] = shm[0];
            csum[((size_t)(b * NH + h)) * M + m] = shs[0];
        }
        __syncthreads();
    }
}

// ---------------- AV: out[b,n,h*64+d] = elu( sum_m p(n,m) * Pk[b,m,h*64+d] ) ----------------
__global__ __launch_bounds__(256) void attn_av(const int* __restrict__ adj, int adjT,
                                               const float* __restrict__ s1,
                                               const float* __restrict__ s2,
                                               const float* __restrict__ cmax,
                                               const float* __restrict__ csum,
                                               const float* __restrict__ Pk,
                                               float* __restrict__ out, int N, int M) {
    const int bh = blockIdx.z;
    const int b = bh >> 3, h = bh & 7;
    const int n0 = blockIdx.y * 64;
    __shared__ float Ps[16][64];   // [m][n] softmax weights
    __shared__ float Ks[16][64];   // [m][d]
    const int tid = threadIdx.x;
    const int tx = tid & 15, ty = tid >> 4;
    const int mm = tid >> 4;
    const int c4 = (tid & 15) << 2;
    const float* s1p = s1 + (size_t)bh * N;
    const float* s2p = s2 + (size_t)bh * M;
    const float* cmp = cmax + (size_t)bh * M;
    const float* csp = csum + (size_t)bh * M;
    float acc[4][4] = {};
    for (int m0 = 0; m0 < M; m0 += 16) {
        int m = m0 + mm;
        float s2v = s2p[m], cm = cmp[m], ics = 1.f / csp[m];
#pragma unroll
        for (int j = 0; j < 4; j++) {
            int n = n0 + c4 + j;
            int a = adjT ? adj[((size_t)(b * M + m)) * N + n]
                         : adj[((size_t)(b * N + n)) * M + m];
            float e;
            if (a > 0) { float x = s1p[n] + s2v; e = x > 0.f ? x : ALPHAF * x; }
            else e = NEGV;
            Ps[mm][c4 + j] = expf(e - cm) * ics;
        }
        float4 kv = *(const float4*)(Pk + ((size_t)(b * M + m)) * NF + h * HD + c4);
        Ks[mm][c4 + 0] = kv.x; Ks[mm][c4 + 1] = kv.y;
        Ks[mm][c4 + 2] = kv.z; Ks[mm][c4 + 3] = kv.w;
        __syncthreads();
#pragma unroll
        for (int k = 0; k < 16; k++) {
            float a_[4], b_[4];
#pragma unroll
            for (int i = 0; i < 4; i++) a_[i] = Ps[k][(ty << 2) + i];
#pragma unroll
            for (int j = 0; j < 4; j++) b_[j] = Ks[k][(tx << 2) + j];
#pragma unroll
            for (int i = 0; i < 4; i++)
#pragma unroll
                for (int j = 0; j < 4; j++) acc[i][j] += a_[i] * b_[j];
        }
        __syncthreads();
    }
#pragma unroll
    for (int i = 0; i < 4; i++) {
        int n = n0 + (ty << 2) + i;
#pragma unroll
        for (int j = 0; j < 4; j++) {
            int d = (tx << 2) + j;
            float v = acc[i][j];
            v = v > 0.f ? v : expm1f(v);
            out[((size_t)(b * N + n)) * NF + h * HD + d] = v;
        }
    }
}

// ---------------- fusion elementwise: out = sig(T2)*T1 + (1-sig)*a ----------------
__global__ void fuse_ew(const float* __restrict__ a, const float* __restrict__ T1,
                        const float* __restrict__ T2, float* __restrict__ out, int n) {
    int i = blockIdx.x * blockDim.x + threadIdx.x;
    if (i < n) {
        float f = 1.f / (1.f + expf(-T2[i]));
        out[i] = f * T1[i] + (1.f - f) * a[i];
    }
}

// ===================== host orchestration =====================
struct Scratch {
    float *Ga, *Ca, *Qa, *G1, *AGG, *Pq, *Pk, *T1, *T2, *Wt;
    float *s1, *s2, *cmax, *csum;
};

static void run_fusion(const float* a, const float* bb,
                       const float* W, const float* U,
                       const float* Wf, const float* Uf,
                       Scratch& S, float* out, int M) {
    dim3 g(NF / 64, M / 64);
    gemm_nn<0><<<g, 256>>>(a,  W,  S.T1, M, NF, NF);
    gemm_nn<1><<<g, 256>>>(bb, U,  S.T1, M, NF, NF);
    gemm_nn<0><<<g, 256>>>(a,  Wf, S.T2, M, NF, NF);
    gemm_nn<1><<<g, 256>>>(bb, Uf, S.T2, M, NF, NF);
    int n = M * NF;
    fuse_ew<<<(n + 255) / 256, 256>>>(a, S.T1, S.T2, out, n);
}

static void run_attn(const float* q, const float* kv, const int* adj, int adjT,
                     int N, int M, const float* W, const float* a1, const float* a2,
                     float* out, Scratch& S) {
    transposeW<<<(NF * NF + 255) / 256, 256>>>(W, S.Wt);
    gemm_nn<0><<<dim3(NF / 64, BATCH * N / 64), 256>>>(q,  S.Wt, S.Pq, BATCH * N, NF, NF);
    gemm_nn<0><<<dim3(NF / 64, BATCH * M / 64), 256>>>(kv, S.Wt, S.Pk, BATCH * M, NF, NF);
    scores_k<<<(BATCH * NH * N + 255) / 256, 256>>>(S.Pq, a1, S.s1, N);
    scores_k<<<(BATCH * NH * M + 255) / 256, 256>>>(S.Pk, a2, S.s2, M);
    colstats_k<<<dim3(M, BATCH), 256>>>(adj, adjT, S.s1, S.s2, S.cmax, S.csum, N, M);
    attn_av<<<dim3(1, N / 64, BATCH * NH), 256>>>(adj, adjT, S.s1, S.s2,
                                                  S.cmax, S.csum, S.Pk, out, N, M);
}

static void run_layer(int l,
                      const float* G, const float* C, const float* Q,
                      float* Gout, float* Cout, float* Qout,
                      const int* g2c, const int* g2q,
                      const float* c2gW, const float* c2ga1, const float* c2ga2,
                      const float* g2qW, const float* g2qa1, const float* g2qa2,
                      const float* q2gW, const float* q2ga1, const float* q2ga2,
                      const float* fusW, const float* fusU,
                      const float* fusWf, const float* fusUf,
                      Scratch& S) {
    const size_t FW = (size_t)NF * NF;
    const size_t AW = (size_t)NH * NF * HD;
    const size_t AV = (size_t)NH * HD;
#define FUS(idx) fusW + (size_t)(l*4+(idx))*FW, fusU + (size_t)(l*4+(idx))*FW, \
                 fusWf + (size_t)(l*4+(idx))*FW, fusUf + (size_t)(l*4+(idx))*FW

    // 1. gloss_same = adj^T @ gloss
    gemm_adjT<<<dim3(NF / 64, NC / 64, BATCH), 256>>>(g2c, G, S.AGG, NG, NC, NF);
    // 2. clip_new = fusion(clip, gloss_same)           [fus idx 0]
    run_fusion(C, S.AGG, FUS(0), S, Cout, BATCH * NC);
    // 3. clip_agg = attn(gloss, clip, g2c)             [c2g]
    run_attn(G, C, g2c, 0, NG, NC, c2gW + l * AW, c2ga1 + l * AV, c2ga2 + l * AV, S.AGG, S);
    // 4. gloss_1 = fusion(gloss, clip_agg)             [fus idx 1]
    run_fusion(G, S.AGG, FUS(1), S, S.G1, BATCH * NG);
    // 5. gloss_agg = attn(question, gloss, g2q^T)      [g2q]
    run_attn(Q, G, g2q, 1, NQ, NG, g2qW + l * AW, g2qa1 + l * AV, g2qa2 + l * AV, S.AGG, S);
    // 6. question_new = fusion(question, gloss_agg)    [fus idx 2]
    run_fusion(Q, S.AGG, FUS(2), S, Qout, BATCH * NQ);
    // 7. question_agg = attn(gloss, question, g2q)     [q2g]
    run_attn(G, Q, g2q, 0, NG, NQ, q2gW + l * AW, q2ga1 + l * AV, q2ga2 + l * AV, S.AGG, S);
    // 8. gloss_new = fusion(gloss_1, question_agg)     [fus idx 3]
    run_fusion(S.G1, S.AGG, FUS(3), S, Gout, BATCH * NG);
#undef FUS
}

static float* symaddr(const void* sym) {
    void* p = nullptr;
    cudaGetSymbolAddress(&p, sym);
    return (float*)p;
}

extern "C" void kernel_launch(void* const* d_in, const int* in_sizes, int n_in,
                              void* d_out, int out_size) {
    (void)in_sizes; (void)n_in; (void)out_size;
    Scratch S;
    S.Ga = symaddr(g_Ga);   S.Ca = symaddr(g_Ca);   S.Qa = symaddr(g_Qa);
    S.G1 = symaddr(g_G1);   S.AGG = symaddr(g_AGG);
    S.Pq = symaddr(g_Pq);   S.Pk = symaddr(g_Pk);
    S.T1 = symaddr(g_T1);   S.T2 = symaddr(g_T2);   S.Wt = symaddr(g_Wt);
    S.s1 = symaddr(g_s1);   S.s2 = symaddr(g_s2);
    S.cmax = symaddr(g_cmax); S.csum = symaddr(g_csum);

    const float* gloss    = (const float*)d_in[0];
    const float* clip     = (const float*)d_in[1];
    const float* question = (const float*)d_in[2];
    const int*   g2c      = (const int*)d_in[3];
    const int*   g2q      = (const int*)d_in[4];
    const float* c2gW  = (const float*)d_in[5];
    const float* c2ga1 = (const float*)d_in[6];
    const float* c2ga2 = (const float*)d_in[7];
    const float* g2qW  = (const float*)d_in[8];
    const float* g2qa1 = (const float*)d_in[9];
    const float* g2qa2 = (const float*)d_in[10];
    const float* q2gW  = (const float*)d_in[11];
    const float* q2ga1 = (const float*)d_in[12];
    const float* q2ga2 = (const float*)d_in[13];
    const float* fusW  = (const float*)d_in[14];
    const float* fusU  = (const float*)d_in[15];
    const float* fusWf = (const float*)d_in[16];
    const float* fusUf = (const float*)d_in[17];

    float* out = (float*)d_out;
    float* outG = out;                                   // gloss  [B,NG,NF]
    float* outC = out + (size_t)BATCH * NG * NF;         // clip   [B,NC,NF]
    float* outQ = outC + (size_t)BATCH * NC * NF;        // question [B,NQ,NF]

    // Layer 0: inputs -> scratch
    run_layer(0, gloss, clip, question, S.Ga, S.Ca, S.Qa,
              g2c, g2q, c2gW, c2ga1, c2ga2, g2qW, g2qa1, g2qa2,
              q2gW, q2ga1, q2ga2, fusW, fusU, fusWf, fusUf, S);
    // Layer 1: scratch -> d_out (fusion kernels write final buffers directly)
    run_layer(1, S.Ga, S.Ca, S.Qa, outG, outC, outQ,
              g2c, g2q, c2gW, c2ga1, c2ga2, g2qW, g2qa1, g2qa2,
              q2gW, q2ga1, q2ga2, fusW, fusU, fusWf, fusUf, S);
}

// round 4
// speedup vs baseline: 1.7499x; 1.7499x over previous
#include <cuda_runtime.h>
#include <cuda_bf16.h>
#include <cstdint>
#include <math.h>

typedef __nv_bfloat16 bf16;
#define B_ 4
#define NG 1024
#define NC 1024
#define NQ 256
#define NF 512
#define NH 8
#define HD 64

// ---------------- helpers ----------------
__device__ __forceinline__ uint32_t smem_u32(const void* p) {
    uint32_t a; asm("{ .reg .u64 t; cvta.to.shared.u64 t, %1; cvt.u32.u64 %0, t; }" : "=r"(a) : "l"(p));
    return a;
}
#define SW128(x) ((x) ^ (((x) >> 3) & 0x70))
__device__ __forceinline__ void ldsm4(uint32_t& r0, uint32_t& r1, uint32_t& r2, uint32_t& r3, uint32_t a) {
    asm volatile("ldmatrix.sync.aligned.m8n8.x4.shared.b16 {%0,%1,%2,%3}, [%4];"
                 : "=r"(r0), "=r"(r1), "=r"(r2), "=r"(r3) : "r"(a));
}
__device__ __forceinline__ void mma_bf16(float* c, const uint32_t* a, const uint32_t* b) {
    asm volatile("mma.sync.aligned.m16n8k16.row.col.f32.bf16.bf16.f32 "
                 "{%0,%1,%2,%3}, {%4,%5,%6,%7}, {%8,%9}, {%0,%1,%2,%3};"
                 : "+f"(c[0]), "+f"(c[1]), "+f"(c[2]), "+f"(c[3])
                 : "r"(a[0]), "r"(a[1]), "r"(a[2]), "r"(a[3]), "r"(b[0]), "r"(b[1]));
}

// ---------------- device scratch ----------------
__device__ bf16 g_fWh[8u*1024*1024], g_fWl[8u*1024*1024];
__device__ bf16 g_aWh[6u*512*512],  g_aWl[6u*512*512];
__device__ bf16 g_adjTb[4u*1024*1024];
__device__ unsigned char g_cg[4u*1024*1024], g_gc[4u*1024*1024];
__device__ unsigned char g_gq[4u*1024*256],  g_qg[4u*256*1024];
__device__ bf16 g_Gth[4u*512*1024], g_Gtl[4u*512*1024];
__device__ bf16 g_cath[4096u*1024], g_catl[4096u*1024];
__device__ bf16 g_Axh[4096u*512],  g_Axl[4096u*512];
__device__ bf16 g_Ph[33554432u], g_Pl[33554432u];
__device__ bf16 g_Vth[2097152u], g_Vtl[2097152u];
__device__ float g_Pq[4096u*512], g_Pk[4096u*512];
__device__ float g_AGG[4096u*512], g_T12[4096u*1024], g_G1[4096u*512];
__device__ float g_Ga[4096u*512], g_Ca[4096u*512], g_Qa[1024u*512];
__device__ float g_s1[32768], g_Ep1[32768], g_En1[32768];
__device__ float g_s2[32768], g_Ep2[32768], g_En2[32768];
__device__ float g_icS[32768];

// ---------------- mma.sync GEMM: D[128,TN] = sum_k A[m,k]*B[n,k], split-bf16 ----------------
// A row-major [M,K] (hi+lo), B row-major [N,K] (hi+lo) == B^T col-major.
// 256 threads, 8 warps. KC=64. 3-pass: AhBh + AhBl + AlBh (2-pass if A exact).
#define SMTOT 65536

template<int NPASS, int TN, int EPI>
__global__ void __launch_bounds__(256) gemm_mm(
    const bf16* __restrict__ Ah, const bf16* __restrict__ Al,
    const bf16* __restrict__ Bh, const bf16* __restrict__ Bl,
    float* __restrict__ C, int K, int lda, int ldb, int ldc,
    long sA, long sB, long sC, int zmode)
{
    constexpr int WN = (TN == 128) ? 4 : 2;
    constexpr int WM = 8 / WN;            // 2 or 4
    constexpr int TMW = 128 / WM;         // 64 or 32
    constexpr int MT = TMW / 16;          // 4 or 2
    constexpr int NT = (TN / WN) / 8;     // 4
    constexpr int A_L = 16384;
    constexpr int B_H = 32768;
    constexpr int B_L = 32768 + TN * 128;
    extern __shared__ char sm[];
    const uint32_t sbase = smem_u32(sm);
    const int tid = threadIdx.x, wid = tid >> 5, lane = tid & 31;
    const int wm = wid / WN, wn = wid % WN;
    const int z = blockIdx.z;
    const int m0 = blockIdx.y * 128, n0 = blockIdx.x * TN;
    const bf16* Azh = Ah + (size_t)z * sA;
    const bf16* Azl = Al + (size_t)z * sA;
    const bf16* Bzh = Bh + (size_t)z * sB;
    const bf16* Bzl = Bl + (size_t)z * sB;
    float* Cz = zmode ? (C + (size_t)(z >> 3) * sC + (z & 7) * 64)
                      : (C + (size_t)z * sC);

    float acc[MT][NT][4];
#pragma unroll
    for (int i = 0; i < MT; i++)
#pragma unroll
        for (int j = 0; j < NT; j++)
#pragma unroll
            for (int v = 0; v < 4; v++) acc[i][j][v] = 0.f;

    const int rsel = lane & 15, csel = lane >> 4;
    const int nch = K >> 6;
    for (int kc = 0; kc < nch; kc++) {
        const int k0 = kc << 6;
        // stage A: 128 rows x 8 16B-chunks, SW128 swizzled
#pragma unroll
        for (int i = tid; i < 128 * 8; i += 256) {
            int r = i >> 3, c = i & 7;
            uint32_t off = SW128((r << 7) + (c << 4));
            size_t go = (size_t)(m0 + r) * lda + k0 + (c << 3);
            *(uint4*)(sm + off) = *(const uint4*)(Azh + go);
            if (NPASS == 3) *(uint4*)(sm + A_L + off) = *(const uint4*)(Azl + go);
        }
#pragma unroll
        for (int i = tid; i < TN * 8; i += 256) {
            int r = i >> 3, c = i & 7;
            uint32_t off = SW128((r << 7) + (c << 4));
            size_t go = (size_t)(n0 + r) * ldb + k0 + (c << 3);
            *(uint4*)(sm + B_H + off) = *(const uint4*)(Bzh + go);
            *(uint4*)(sm + B_L + off) = *(const uint4*)(Bzl + go);
        }
        __syncthreads();
#pragma unroll
        for (int ks = 0; ks < 4; ks++) {
            uint32_t ah[MT][4], al[MT][4], bh[NT][2], bl[NT][2];
#pragma unroll
            for (int mt = 0; mt < MT; mt++) {
                int row = wm * TMW + mt * 16 + rsel;
                uint32_t a_ = sbase + SW128((row << 7) + ((ks * 2 + csel) << 4));
                ldsm4(ah[mt][0], ah[mt][1], ah[mt][2], ah[mt][3], a_);
                if (NPASS == 3)
                    ldsm4(al[mt][0], al[mt][1], al[mt][2], al[mt][3], a_ + A_L);
            }
#pragma unroll
            for (int np = 0; np < NT / 2; np++) {
                int nr = wn * (TN / WN) + np * 16 + rsel;
                uint32_t b_ = sbase + B_H + SW128((nr << 7) + ((ks * 2 + csel) << 4));
                uint32_t r0, r1, r2, r3;
                ldsm4(r0, r1, r2, r3, b_);
                bh[2*np][0] = r0; bh[2*np+1][0] = r1; bh[2*np][1] = r2; bh[2*np+1][1] = r3;
                ldsm4(r0, r1, r2, r3, b_ + (B_L - B_H));
                bl[2*np][0] = r0; bl[2*np+1][0] = r1; bl[2*np][1] = r2; bl[2*np+1][1] = r3;
            }
#pragma unroll
            for (int mt = 0; mt < MT; mt++)
#pragma unroll
                for (int nt = 0; nt < NT; nt++) {
                    mma_bf16(acc[mt][nt], ah[mt], bh[nt]);
                    mma_bf16(acc[mt][nt], ah[mt], bl[nt]);
                    if (NPASS == 3) mma_bf16(acc[mt][nt], al[mt], bh[nt]);
                }
        }
        __syncthreads();
    }
    // epilogue
#pragma unroll
    for (int mt = 0; mt < MT; mt++) {
        int row = m0 + wm * TMW + mt * 16 + (lane >> 2);
#pragma unroll
        for (int nt = 0; nt < NT; nt++) {
            int col = n0 + wn * (TN / WN) + nt * 8 + ((lane & 3) << 1);
            float v0 = acc[mt][nt][0], v1 = acc[mt][nt][1];
            float v2 = acc[mt][nt][2], v3 = acc[mt][nt][3];
            if (EPI == 1) {
                v0 = v0 > 0.f ? v0 : expm1f(v0);
                v1 = v1 > 0.f ? v1 : expm1f(v1);
                v2 = v2 > 0.f ? v2 : expm1f(v2);
                v3 = v3 > 0.f ? v3 : expm1f(v3);
            }
            float2 p0 = {v0, v1}, p1 = {v2, v3};
            *(float2*)&Cz[(size_t)row * ldc + col] = p0;
            *(float2*)&Cz[(size_t)(row + 8) * ldc + col] = p1;
        }
    }
}

// ---------------- prep kernels ----------------
__global__ void prep_fusW(const float* W, const float* U, const float* Wf, const float* Uf) {
    int i = blockIdx.x * 256 + threadIdx.x;           // n*1024+k
    int zi = blockIdx.y;                              // l*4+idx
    if (i >= 1024 * 1024) return;
    int n = i >> 10, k = i & 1023;
    size_t base = (size_t)zi * 512 * 512;
    float v;
    if (n < 512) v = (k < 512) ? W[base + (size_t)k*512 + n] : U[base + (size_t)(k-512)*512 + n];
    else         v = (k < 512) ? Wf[base + (size_t)k*512 + (n-512)] : Uf[base + (size_t)(k-512)*512 + (n-512)];
    bf16 h = __float2bfloat16(v);
    g_fWh[(size_t)zi * 1048576 + i] = h;
    g_fWl[(size_t)zi * 1048576 + i] = __float2bfloat16(v - __bfloat162float(h));
}
__global__ void prep_attW(const float* W, int slot) {
    int i = blockIdx.x * 256 + threadIdx.x;           // n*512+k, n=h*64+d
    if (i >= 512 * 512) return;
    int n = i >> 9, k = i & 511;
    float v = W[((size_t)((n >> 6) * 512 + k)) * 64 + (n & 63)];
    bf16 h = __float2bfloat16(v);
    g_aWh[(size_t)slot * 262144 + i] = h;
    g_aWl[(size_t)slot * 262144 + i] = __float2bfloat16(v - __bfloat162float(h));
}
__global__ void prep_adj_cg(const int* adj) {        // g2c [b][g][c]
    int i = blockIdx.x * 256 + threadIdx.x; int b = blockIdx.y;
    if (i >= NG * NC) return;
    int gi = i >> 10, c = i & 1023;
    int a = adj[(size_t)b * NG * NC + i];
    unsigned char u = (a > 0);
    g_gc[(size_t)b * NG * NC + i] = u;
    size_t t = (size_t)b * NG * NC + (size_t)c * NG + gi;
    g_cg[t] = u;
    g_adjTb[t] = __float2bfloat16((float)a);
}
__global__ void prep_adj_gq(const int* adj) {        // g2q [b][g][q]
    int i = blockIdx.x * 256 + threadIdx.x; int b = blockIdx.y;
    if (i >= NG * NQ) return;
    int gi = i >> 8, q = i & 255;
    unsigned char u = (adj[(size_t)b * NG * NQ + i] > 0);
    g_gq[(size_t)b * NG * NQ + i] = u;
    g_qg[(size_t)b * NQ * NG + (size_t)q * NG + gi] = u;
}
__global__ void split_k(const float* __restrict__ src, bf16* dh, bf16* dl,
                        int total, int ostride, int coff) {
    int i = blockIdx.x * 256 + threadIdx.x;
    if (i >= total) return;
    int m = i >> 9, f = i & 511;
    float v = src[i];
    bf16 h = __float2bfloat16(v);
    size_t o = (size_t)m * ostride + coff + f;
    dh[o] = h; dl[o] = __float2bfloat16(v - __bfloat162float(h));
}
__global__ void tsplit_k(const float* __restrict__ src) {   // [b][g][f] -> [b][f][g]
    int i = blockIdx.x * 256 + threadIdx.x; int b = blockIdx.y;
    if (i >= NF * NG) return;
    int f = i >> 10, gi = i & 1023;
    float v = src[((size_t)b * NG + gi) * NF + f];
    bf16 h = __float2bfloat16(v);
    size_t o = (size_t)b * NF * NG + i;
    g_Gth[o] = h; g_Gtl[o] = __float2bfloat16(v - __bfloat162float(h));
}
__global__ void scoresE(const float* __restrict__ P, const float* __restrict__ a,
                        float* s, float* Ep, float* En, int Nt) {
    int i = blockIdx.x * 256 + threadIdx.x;
    if (i >= B_ * NH * Nt) return;
    int n = i % Nt, bh = i / Nt, h = bh & 7, b = bh >> 3;
    const float* row = P + ((size_t)b * Nt + n) * NF + h * HD;
    const float* av = a + h * HD;
    float acc = 0.f;
#pragma unroll
    for (int d = 0; d < 64; d++) acc += row[d] * av[d];
    s[i] = acc; Ep[i] = expf(acc); En[i] = expf(0.2f * acc);
}
__global__ void colsum_k(const unsigned char* __restrict__ adjmn,
                         const float* __restrict__ s1, const float* __restrict__ Ep1,
                         const float* __restrict__ En1,
                         const float* __restrict__ Ep2, const float* __restrict__ En2,
                         const float* __restrict__ s2, float* icS, int N, int M) {
    int b = blockIdx.y;
    int w = threadIdx.x >> 5, lane = threadIdx.x & 31;
    int m = blockIdx.x * 8 + w;
    if (m >= M) return;
    const unsigned char* arow = adjmn + ((size_t)b * M + m) * N;
    float s2v[8], Sp[8] = {}, Sn[8] = {};
#pragma unroll
    for (int h = 0; h < 8; h++) s2v[h] = s2[((size_t)(b * 8 + h)) * M + m];
    for (int n = lane; n < N; n += 32) {
        if (!arow[n]) continue;
#pragma unroll
        for (int h = 0; h < 8; h++) {
            size_t o = ((size_t)(b * 8 + h)) * N + n;
            if (s1[o] + s2v[h] > 0.f) Sp[h] += Ep1[o]; else Sn[h] += En1[o];
        }
    }
#pragma unroll
    for (int h = 0; h < 8; h++) {
        float p = Sp[h], q = Sn[h];
        for (int d = 16; d; d >>= 1) { p += __shfl_xor_sync(~0u, p, d); q += __shfl_xor_sync(~0u, q, d); }
        if (lane == 0) {
            size_t o = ((size_t)(b * 8 + h)) * M + m;
            icS[o] = 1.f / (Ep2[o] * p + En2[o] * q);
        }
    }
}
__global__ void pbuild_k(const unsigned char* __restrict__ adjnm,
                         const float* __restrict__ s1, const float* __restrict__ Ep1,
                         const float* __restrict__ En1,
                         const float* __restrict__ s2, const float* __restrict__ Ep2,
                         const float* __restrict__ En2, int N, int M) {
    int z = blockIdx.z, b = z >> 3;
    int n = blockIdx.y;
    int m0 = (blockIdx.x * 256 + threadIdx.x) * 4;
    if (m0 >= M) return;
    uchar4 a4 = *(const uchar4*)(adjnm + ((size_t)b * N + n) * M + m0);
    unsigned char aa[4] = {a4.x, a4.y, a4.z, a4.w};
    size_t o1 = (size_t)z * N + n;
    float s1v = s1[o1], p1 = Ep1[o1], n1 = En1[o1];
    bf16 hv[4], lv[4];
#pragma unroll
    for (int j = 0; j < 4; j++) {
        size_t o2 = (size_t)z * M + m0 + j;
        float w = 0.f;
        if (aa[j]) w = (s1v + s2[o2] > 0.f) ? p1 * Ep2[o2] : n1 * En2[o2];
        hv[j] = __float2bfloat16(w);
        lv[j] = __float2bfloat16(w - __bfloat162float(hv[j]));
    }
    size_t o = (size_t)z * N * M + (size_t)n * M + m0;
    *(uint2*)(g_Ph + o) = *(uint2*)hv;
    *(uint2*)(g_Pl + o) = *(uint2*)lv;
}
__global__ void vtprep_k(const float* __restrict__ Pk, const float* __restrict__ icS, int M) {
    int z = blockIdx.z, b = z >> 3, h = z & 7;
    int i = blockIdx.x * 256 + threadIdx.x;   // d*M+m
    if (i >= 64 * M) return;
    int d = i / M, m = i % M;
    float v = Pk[((size_t)b * M + m) * NF + h * 64 + d] * icS[(size_t)z * M + m];
    bf16 hh = __float2bfloat16(v);
    size_t o = (size_t)z * 64 * M + i;
    g_Vth[o] = hh; g_Vtl[o] = __float2bfloat16(v - __bfloat162float(hh));
}
__global__ void fuse_ew(const float* __restrict__ a, const float* __restrict__ T12,
                        float* __restrict__ out, int total) {
    int i = blockIdx.x * 256 + threadIdx.x;
    if (i >= total) return;
    int m = i >> 9, f = i & 511;
    float t1 = T12[(size_t)m * 1024 + f], t2 = T12[(size_t)m * 1024 + 512 + f];
    float g = 1.f / (1.f + expf(-t2));
    out[i] = g * t1 + (1.f - g) * a[i];
}

// ---------------- host ----------------
template<typename T> static T* sa(const void* s) { void* p = nullptr; cudaGetSymbolAddress(&p, s); return (T*)p; }

struct Ctx {
    bf16 *fWh, *fWl, *aWh, *aWl, *adjTb, *Gth, *Gtl, *cath, *catl, *Axh, *Axl, *Ph, *Pl, *Vth, *Vtl;
    unsigned char *cg, *gc, *gq, *qg;
    float *Pq, *Pk, *AGG, *T12, *G1, *Ga, *Ca, *Qa;
    float *s1, *Ep1, *En1, *s2, *Ep2, *En2, *icS;
};

static void run_fusion(Ctx& X, int l, int idx, const float* a, const float* bpart,
                       float* out, int Mrows) {
    int tot = Mrows * 512;
    split_k<<<(tot + 255) / 256, 256>>>(a, X.cath, X.catl, tot, 1024, 0);
    split_k<<<(tot + 255) / 256, 256>>>(bpart, X.cath, X.catl, tot, 1024, 512);
    const bf16* wh = X.fWh + (size_t)(l * 4 + idx) * 1048576;
    const bf16* wl = X.fWl + (size_t)(l * 4 + idx) * 1048576;
    gemm_mm<3, 128, 0><<<dim3(8, Mrows / 128, 1), 256, SMTOT>>>(
        X.cath, X.catl, wh, wl, X.T12, 1024, 1024, 1024, 1024, 0, 0, 0, 0);
    fuse_ew<<<(tot + 255) / 256, 256>>>(a, X.T12, out, tot);
}

static void run_attn(Ctx& X, int l, int which, const float* q, const float* kv,
                     int Nn, int Mkv, const unsigned char* adj_mn, const unsigned char* adj_nm,
                     const float* a1, const float* a2, float* out) {
    int slot = l * 3 + which;
    const bf16* wh = X.aWh + (size_t)slot * 262144;
    const bf16* wl = X.aWl + (size_t)slot * 262144;
    int tq = B_ * Nn * 512, tk = B_ * Mkv * 512;
    split_k<<<(tq + 255) / 256, 256>>>(q, X.Axh, X.Axl, tq, 512, 0);
    gemm_mm<3, 128, 0><<<dim3(4, B_ * Nn / 128, 1), 256, SMTOT>>>(
        X.Axh, X.Axl, wh, wl, X.Pq, 512, 512, 512, 512, 0, 0, 0, 0);
    split_k<<<(tk + 255) / 256, 256>>>(kv, X.Axh, X.Axl, tk, 512, 0);
    gemm_mm<3, 128, 0><<<dim3(4, B_ * Mkv / 128, 1), 256, SMTOT>>>(
        X.Axh, X.Axl, wh, wl, X.Pk, 512, 512, 512, 512, 0, 0, 0, 0);
    scoresE<<<(B_ * NH * Nn + 255) / 256, 256>>>(X.Pq, a1 + l * 512, X.s1, X.Ep1, X.En1, Nn);
    scoresE<<<(B_ * NH * Mkv + 255) / 256, 256>>>(X.Pk, a2 + l * 512, X.s2, X.Ep2, X.En2, Mkv);
    colsum_k<<<dim3((Mkv + 7) / 8, B_), 256>>>(adj_mn, X.s1, X.Ep1, X.En1, X.Ep2, X.En2, X.s2, X.icS, Nn, Mkv);
    vtprep_k<<<dim3((64 * Mkv + 255) / 256, 1, 32), 256>>>(X.Pk, X.icS, Mkv);
    pbuild_k<<<dim3((Mkv / 4 + 255) / 256, Nn, 32), 256>>>(adj_nm, X.s1, X.Ep1, X.En1, X.s2, X.Ep2, X.En2, Nn, Mkv);
    gemm_mm<3, 64, 1><<<dim3(1, Nn / 128, 32), 256, SMTOT>>>(
        X.Ph, X.Pl, X.Vth, X.Vtl, out, Mkv, Mkv, Mkv, 512,
        (long)Nn * Mkv, (long)64 * Mkv, (long)Nn * 512, 1);
}

static void run_layer(Ctx& X, int l, const float* G, const float* C, const float* Q,
                      float* Gout, float* Cout, float* Qout,
                      const float* c2ga1, const float* c2ga2,
                      const float* g2qa1, const float* g2qa2,
                      const float* q2ga1, const float* q2ga2) {
    // gloss_same = adj^T @ gloss
    tsplit_k<<<dim3((NF * NG) / 256, B_), 256>>>(G);
    gemm_mm<2, 128, 0><<<dim3(4, 8, B_), 256, SMTOT>>>(
        X.adjTb, X.adjTb, X.Gth, X.Gtl, X.AGG, 1024, 1024, 1024, 512,
        (long)NG * NC, (long)NF * NG, (long)NC * NF, 0);
    run_fusion(X, l, 0, C, X.AGG, Cout, B_ * NC);                      // clip_new
    run_attn(X, l, 0, G, C, NG, NC, X.cg, X.gc, c2ga1, c2ga2, X.AGG);  // clip_agg
    run_fusion(X, l, 1, G, X.AGG, X.G1, B_ * NG);                      // gloss_1
    run_attn(X, l, 1, Q, G, NQ, NG, X.gq, X.qg, g2qa1, g2qa2, X.AGG);  // gloss_agg
    run_fusion(X, l, 2, Q, X.AGG, Qout, B_ * NQ);                      // question_new
    run_attn(X, l, 2, G, Q, NG, NQ, X.qg, X.gq, q2ga1, q2ga2, X.AGG);  // question_agg
    run_fusion(X, l, 3, X.G1, X.AGG, Gout, B_ * NG);                   // gloss_new
}

extern "C" void kernel_launch(void* const* d_in, const int* in_sizes, int n_in,
                              void* d_out, int out_size) {
    (void)in_sizes; (void)n_in; (void)out_size;
    Ctx X;
    X.fWh = sa<bf16>(g_fWh); X.fWl = sa<bf16>(g_fWl);
    X.aWh = sa<bf16>(g_aWh); X.aWl = sa<bf16>(g_aWl);
    X.adjTb = sa<bf16>(g_adjTb);
    X.Gth = sa<bf16>(g_Gth); X.Gtl = sa<bf16>(g_Gtl);
    X.cath = sa<bf16>(g_cath); X.catl = sa<bf16>(g_catl);
    X.Axh = sa<bf16>(g_Axh); X.Axl = sa<bf16>(g_Axl);
    X.Ph = sa<bf16>(g_Ph); X.Pl = sa<bf16>(g_Pl);
    X.Vth = sa<bf16>(g_Vth); X.Vtl = sa<bf16>(g_Vtl);
    X.cg = sa<unsigned char>(g_cg); X.gc = sa<unsigned char>(g_gc);
    X.gq = sa<unsigned char>(g_gq); X.qg = sa<unsigned char>(g_qg);
    X.Pq = sa<float>(g_Pq); X.Pk = sa<float>(g_Pk);
    X.AGG = sa<float>(g_AGG); X.T12 = sa<float>(g_T12); X.G1 = sa<float>(g_G1);
    X.Ga = sa<float>(g_Ga); X.Ca = sa<float>(g_Ca); X.Qa = sa<float>(g_Qa);
    X.s1 = sa<float>(g_s1); X.Ep1 = sa<float>(g_Ep1); X.En1 = sa<float>(g_En1);
    X.s2 = sa<float>(g_s2); X.Ep2 = sa<float>(g_Ep2); X.En2 = sa<float>(g_En2);
    X.icS = sa<float>(g_icS);

    cudaFuncSetAttribute(gemm_mm<2,128,0>, cudaFuncAttributeMaxDynamicSharedMemorySize, SMTOT);
    cudaFuncSetAttribute(gemm_mm<3,128,0>, cudaFuncAttributeMaxDynamicSharedMemorySize, SMTOT);
    cudaFuncSetAttribute(gemm_mm<3,64,1>,  cudaFuncAttributeMaxDynamicSharedMemorySize, SMTOT);

    const float* gloss    = (const float*)d_in[0];
    const float* clip     = (const float*)d_in[1];
    const float* question = (const float*)d_in[2];
    const int*   g2c      = (const int*)d_in[3];
    const int*   g2q      = (const int*)d_in[4];
    const float* c2gW  = (const float*)d_in[5];
    const float* c2ga1 = (const float*)d_in[6];
    const float* c2ga2 = (const float*)d_in[7];
    const float* g2qW  = (const float*)d_in[8];
    const float* g2qa1 = (const float*)d_in[9];
    const float* g2qa2 = (const float*)d_in[10];
    const float* q2gW  = (const float*)d_in[11];
    const float* q2ga1 = (const float*)d_in[12];
    const float* q2ga2 = (const float*)d_in[13];
    const float* fusW  = (const float*)d_in[14];
    const float* fusU  = (const float*)d_in[15];
    const float* fusWf = (const float*)d_in[16];
    const float* fusUf = (const float*)d_in[17];

    prep_fusW<<<dim3(4096, 8), 256>>>(fusW, fusU, fusWf, fusUf);
    const size_t AW = (size_t)NH * NF * HD;
    for (int l = 0; l < 2; l++) {
        prep_attW<<<1024, 256>>>(c2gW + l * AW, l * 3 + 0);
        prep_attW<<<1024, 256>>>(g2qW + l * AW, l * 3 + 1);
        prep_attW<<<1024, 256>>>(q2gW + l * AW, l * 3 + 2);
    }
    prep_adj_cg<<<dim3(4096, B_), 256>>>(g2c);
    prep_adj_gq<<<dim3(1024, B_), 256>>>(g2q);

    float* out = (float*)d_out;
    float* outG = out;
    float* outC = out + (size_t)B_ * NG * NF;
    float* outQ = outC + (size_t)B_ * NC * NF;

    run_layer(X, 0, gloss, clip, question, X.Ga, X.Ca, X.Qa,
              c2ga1, c2ga2, g2qa1, g2qa2, q2ga1, q2ga2);
    run_layer(X, 1, X.Ga, X.Ca, X.Qa, outG, outC, outQ,
              c2ga1, c2ga2, g2qa1, g2qa2, q2ga1, q2ga2);
}

// round 6
// speedup vs baseline: 1.9431x; 1.1104x over previous
#include <cuda_runtime.h>
#include <cuda_bf16.h>
#include <cstdint>
#include <math.h>

typedef __nv_bfloat16 bf16;
#define B_ 4
#define NG 1024
#define NC 1024
#define NQ 256
#define NF 512
#define NH 8
#define HD 64

// ---------------- helpers ----------------
__device__ __forceinline__ uint32_t smem_u32(const void* p) {
    uint32_t a; asm("{ .reg .u64 t; cvta.to.shared.u64 t, %1; cvt.u32.u64 %0, t; }" : "=r"(a) : "l"(p));
    return a;
}
#define SW128(x) ((x) ^ (((x) >> 3) & 0x70))
__device__ __forceinline__ void ldsm4(uint32_t& r0, uint32_t& r1, uint32_t& r2, uint32_t& r3, uint32_t a) {
    asm volatile("ldmatrix.sync.aligned.m8n8.x4.shared.b16 {%0,%1,%2,%3}, [%4];"
                 : "=r"(r0), "=r"(r1), "=r"(r2), "=r"(r3) : "r"(a));
}
__device__ __forceinline__ void mma_bf16(float* c, const uint32_t* a, const uint32_t* b) {
    asm volatile("mma.sync.aligned.m16n8k16.row.col.f32.bf16.bf16.f32 "
                 "{%0,%1,%2,%3}, {%4,%5,%6,%7}, {%8,%9}, {%0,%1,%2,%3};"
                 : "+f"(c[0]), "+f"(c[1]), "+f"(c[2]), "+f"(c[3])
                 : "r"(a[0]), "r"(a[1]), "r"(a[2]), "r"(a[3]), "r"(b[0]), "r"(b[1]));
}
#define CP16(d, s) asm volatile("cp.async.cg.shared.global [%0], [%1], 16;" :: "r"(d), "l"(s))
#define CPC() asm volatile("cp.async.commit_group;" ::: "memory")
template<int N> __device__ __forceinline__ void cpwait() {
    asm volatile("cp.async.wait_group %0;" :: "n"(N) : "memory");
}
__device__ __forceinline__ uint32_t pack2(bf16 a, bf16 b) {
    return (uint32_t)__bfloat16_as_ushort(a) | ((uint32_t)__bfloat16_as_ushort(b) << 16);
}

// ---------------- device scratch ----------------
__device__ bf16 g_fWh[8u*1024*1024], g_fWl[8u*1024*1024];
__device__ bf16 g_aWh[6u*512*512],  g_aWl[6u*512*512];
__device__ bf16 g_adjTb[4u*1024*1024];
__device__ unsigned char g_cg[4u*1024*1024], g_gc[4u*1024*1024];
__device__ unsigned char g_gq[4u*1024*256],  g_qg[4u*256*1024];
__device__ bf16 g_Gth[4u*512*1024], g_Gtl[4u*512*1024];
__device__ bf16 g_cath[4096u*1024], g_catl[4096u*1024];
__device__ bf16 g_Axh[4096u*512],  g_Axl[4096u*512];
__device__ bf16 g_Vth[2097152u], g_Vtl[2097152u];
__device__ float g_Pq[4096u*512], g_Pk[4096u*512];
__device__ float g_T12[4096u*1024], g_G1[4096u*512];
__device__ float g_Ga[4096u*512], g_Ca[4096u*512], g_Qa[1024u*512];
__device__ float g_s1[32768], g_Ep1[32768], g_En1[32768];
__device__ float g_s2[32768], g_Ep2[32768], g_En2[32768];
__device__ float g_icS[32768];

// ---------------- pipelined mma.sync GEMM ----------------
// D[128,TN] = sum_k A[m,k]*B[n,k]. A row-major [M,K] (hi+lo), B row-major [N,K] (hi+lo).
// 2-stage cp.async pipeline, KC=64. NPASS=3: AhBh+AhBl+AlBh; NPASS=2: A exact.
// EPI: 0 = fp32 store; 2 = split-bf16 store to Dh/Dl.
template<int NPASS, int TN>
__device__ __forceinline__ void stage_chunk(uint32_t sdst, const char* smbase,
    const bf16* Ah, const bf16* Al, const bf16* Bh, const bf16* Bl,
    int lda, int ldb, int m0, int n0, int k0, int tid)
{
    constexpr int ASZ = 16384;
    constexpr int ABY = (NPASS == 3) ? 32768 : 16384;
    constexpr int BSZ = TN * 128;
    (void)smbase;
#pragma unroll 2
    for (int i = tid; i < 128 * 8; i += 256) {
        int r = i >> 3, c = i & 7;
        uint32_t off = SW128((r << 7) + (c << 4));
        size_t go = (size_t)(m0 + r) * lda + k0 + (c << 3);
        CP16(sdst + off, Ah + go);
        if (NPASS == 3) CP16(sdst + ASZ + off, Al + go);
    }
#pragma unroll 2
    for (int i = tid; i < TN * 8; i += 256) {
        int r = i >> 3, c = i & 7;
        uint32_t off = SW128((r << 7) + (c << 4));
        size_t go = (size_t)(n0 + r) * ldb + k0 + (c << 3);
        CP16(sdst + ABY + off, Bh + go);
        CP16(sdst + ABY + BSZ + off, Bl + go);
    }
    CPC();
}

template<int NPASS, int TN, int EPI>
__global__ void __launch_bounds__(256) gemm_mm(
    const bf16* __restrict__ Ah, const bf16* __restrict__ Al,
    const bf16* __restrict__ Bh, const bf16* __restrict__ Bl,
    float* __restrict__ C, bf16* __restrict__ Dh, bf16* __restrict__ Dl,
    int K, int lda, int ldb, int ldc, long sA, long sB, long sC)
{
    constexpr int WN = 4;
    constexpr int WM = 2;
    constexpr int TMW = 64;
    constexpr int MT = 4;
    constexpr int NT = (TN / WN) / 8;      // 4 for TN=128
    constexpr int ASZ = 16384;
    constexpr int ABY = (NPASS == 3) ? 32768 : 16384;
    constexpr int BSZ = TN * 128;
    constexpr int STG = ABY + 2 * BSZ;
    extern __shared__ char sm[];
    const uint32_t sbase = smem_u32(sm);
    const int tid = threadIdx.x, lane = tid & 31;
    const int wid = tid >> 5;
    const int wm = wid / WN, wn = wid % WN;
    const int z = blockIdx.z;
    const int m0 = blockIdx.y * 128, n0 = blockIdx.x * TN;
    const bf16* Azh = Ah + (size_t)z * sA;
    const bf16* Azl = Al + (size_t)z * sA;
    const bf16* Bzh = Bh + (size_t)z * sB;
    const bf16* Bzl = Bl + (size_t)z * sB;

    float acc[MT][NT][4];
#pragma unroll
    for (int i = 0; i < MT; i++)
#pragma unroll
        for (int j = 0; j < NT; j++)
#pragma unroll
            for (int v = 0; v < 4; v++) acc[i][j][v] = 0.f;

    const int rsel = lane & 15, csel = lane >> 4;
    const int nch = K >> 6;
    stage_chunk<NPASS, TN>(sbase, sm, Azh, Azl, Bzh, Bzl, lda, ldb, m0, n0, 0, tid);
    for (int kc = 0; kc < nch; kc++) {
        if (kc + 1 < nch) {
            stage_chunk<NPASS, TN>(sbase + ((kc + 1) & 1) * STG, sm, Azh, Azl, Bzh, Bzl,
                                   lda, ldb, m0, n0, (kc + 1) << 6, tid);
            cpwait<1>();
        } else {
            cpwait<0>();
        }
        __syncthreads();
        const uint32_t aH = sbase + (kc & 1) * STG;
        const uint32_t aL = aH + ASZ;
        const uint32_t bH = aH + ABY;
        const uint32_t bL = bH + BSZ;
#pragma unroll
        for (int ks = 0; ks < 4; ks++) {
            uint32_t ah[MT][4], al[MT][4], bh[NT][2], bl[NT][2];
#pragma unroll
            for (int mt = 0; mt < MT; mt++) {
                int row = wm * TMW + mt * 16 + rsel;
                uint32_t off = SW128((row << 7) + ((ks * 2 + csel) << 4));
                ldsm4(ah[mt][0], ah[mt][1], ah[mt][2], ah[mt][3], aH + off);
                if (NPASS == 3)
                    ldsm4(al[mt][0], al[mt][1], al[mt][2], al[mt][3], aL + off);
            }
#pragma unroll
            for (int np = 0; np < NT / 2; np++) {
                int nr = wn * (TN / WN) + np * 16 + rsel;
                uint32_t off = SW128((nr << 7) + ((ks * 2 + csel) << 4));
                uint32_t r0, r1, r2, r3;
                ldsm4(r0, r1, r2, r3, bH + off);
                bh[2*np][0] = r0; bh[2*np+1][0] = r1; bh[2*np][1] = r2; bh[2*np+1][1] = r3;
                ldsm4(r0, r1, r2, r3, bL + off);
                bl[2*np][0] = r0; bl[2*np+1][0] = r1; bl[2*np][1] = r2; bl[2*np+1][1] = r3;
            }
#pragma unroll
            for (int mt = 0; mt < MT; mt++)
#pragma unroll
                for (int nt = 0; nt < NT; nt++) {
                    mma_bf16(acc[mt][nt], ah[mt], bh[nt]);
                    mma_bf16(acc[mt][nt], ah[mt], bl[nt]);
                    if (NPASS == 3) mma_bf16(acc[mt][nt], al[mt], bh[nt]);
                }
        }
        __syncthreads();
    }
    if (EPI == 0) {
        float* Cz = C + (size_t)z * sC;
#pragma unroll
        for (int mt = 0; mt < MT; mt++) {
            int row = m0 + wm * TMW + mt * 16 + (lane >> 2);
#pragma unroll
            for (int nt = 0; nt < NT; nt++) {
                int col = n0 + wn * (TN / WN) + nt * 8 + ((lane & 3) << 1);
                float2 p0 = {acc[mt][nt][0], acc[mt][nt][1]};
                float2 p1 = {acc[mt][nt][2], acc[mt][nt][3]};
                *(float2*)&Cz[(size_t)row * ldc + col] = p0;
                *(float2*)&Cz[(size_t)(row + 8) * ldc + col] = p1;
            }
        }
    } else {
        bf16* Dzh = Dh + (size_t)z * sC;
        bf16* Dzl = Dl + (size_t)z * sC;
#pragma unroll
        for (int mt = 0; mt < MT; mt++) {
            int row = m0 + wm * TMW + mt * 16 + (lane >> 2);
#pragma unroll
            for (int nt = 0; nt < NT; nt++) {
                int col = n0 + wn * (TN / WN) + nt * 8 + ((lane & 3) << 1);
                float v0 = acc[mt][nt][0], v1 = acc[mt][nt][1];
                float v2 = acc[mt][nt][2], v3 = acc[mt][nt][3];
                bf16 h0 = __float2bfloat16(v0), h1 = __float2bfloat16(v1);
                bf16 h2 = __float2bfloat16(v2), h3 = __float2bfloat16(v3);
                *(uint32_t*)&Dzh[(size_t)row * ldc + col] = pack2(h0, h1);
                *(uint32_t*)&Dzh[(size_t)(row + 8) * ldc + col] = pack2(h2, h3);
                *(uint32_t*)&Dzl[(size_t)row * ldc + col] =
                    pack2(__float2bfloat16(v0 - __bfloat162float(h0)),
                          __float2bfloat16(v1 - __bfloat162float(h1)));
                *(uint32_t*)&Dzl[(size_t)(row + 8) * ldc + col] =
                    pack2(__float2bfloat16(v2 - __bfloat162float(h2)),
                          __float2bfloat16(v3 - __bfloat162float(h3)));
            }
        }
    }
}

// ---------------- fused attention AV (P built on the fly) ----------------
// out[b, n, h*64+d] = elu( sum_m P[z][n][m] * Vt[z][d][m] ), z = b*8+h.
// P computed from adj + separable score factors during A-tile staging.
// Output: split bf16 into Dh/Dl (concat buffer col 512), ld 1024.
__global__ void __launch_bounds__(256) attn_av2(
    const unsigned char* __restrict__ adjnm,
    const float* __restrict__ s1, const float* __restrict__ Ep1, const float* __restrict__ En1,
    const float* __restrict__ s2, const float* __restrict__ Ep2, const float* __restrict__ En2,
    const bf16* __restrict__ Vth, const bf16* __restrict__ Vtl,
    bf16* __restrict__ Dh, bf16* __restrict__ Dl, int N, int M)
{
    constexpr int ASZ = 16384;          // 128 n x 64 m x2B
    constexpr int ABY = 32768;
    constexpr int BSZ = 8192;           // 64 d x 64 m x2B
    constexpr int STG = ABY + 2 * BSZ;  // 49152
    constexpr int TN = 64, WN = 2, TMW = 32, MT = 2, NT = 4;
    extern __shared__ char sm[];
    const uint32_t sbase = smem_u32(sm);
    const int tid = threadIdx.x, lane = tid & 31;
    const int wid = tid >> 5;
    const int wm = wid >> 1, wn = wid & 1;
    const int z = blockIdx.z, b = z >> 3;
    const int n0 = blockIdx.y * 128;
    const bf16* Vzh = Vth + (size_t)z * 64 * M;
    const bf16* Vzl = Vtl + (size_t)z * 64 * M;
    const size_t zN = (size_t)z * N, zM = (size_t)z * M;

    // per-n constants for this thread's staging row
    const int nl = tid & 127, half = tid >> 7;
    const int ng = n0 + nl;
    const float s1v = s1[zN + ng], p1 = Ep1[zN + ng], n1v = En1[zN + ng];
    const unsigned char* arow = adjnm + ((size_t)b * N + ng) * M;
    const uint32_t rowoff = (nl << 7) + (half << 6);

    // ---- staging helpers (inlined twice) ----
#define STAGE_B(kc, st) do { \
    const int k0_ = (kc) << 6; \
    const uint32_t sd_ = sbase + (st) * STG + ABY; \
    for (int i = tid; i < 64 * 8; i += 256) { \
        int r_ = i >> 3, c_ = i & 7; \
        uint32_t off_ = SW128((r_ << 7) + (c_ << 4)); \
        size_t go_ = (size_t)r_ * M + k0_ + (c_ << 3); \
        CP16(sd_ + off_, Vzh + go_); \
        CP16(sd_ + BSZ + off_, Vzl + go_); \
    } \
    CPC(); } while (0)

#define BUILD_A(kc, st) do { \
    const int mb_ = ((kc) << 6) + half * 32; \
    union { uint4 v; unsigned char c[16]; } a0_, a1_; \
    a0_.v = *(const uint4*)(arow + mb_); \
    a1_.v = *(const uint4*)(arow + mb_ + 16); \
    float wv_[32]; \
    _Pragma("unroll") \
    for (int j = 0; j < 32; j++) { \
        unsigned char aj = (j < 16) ? a0_.c[j] : a1_.c[j - 16]; \
        float w = 0.f; \
        if (aj) { \
            size_t o2 = zM + mb_ + j; \
            w = (s1v + s2[o2] > 0.f) ? p1 * Ep2[o2] : n1v * En2[o2]; \
        } \
        wv_[j] = w; \
    } \
    char* dst_ = sm + (st) * STG; \
    _Pragma("unroll") \
    for (int g = 0; g < 4; g++) { \
        uint32_t hp_[4], lp_[4]; \
        _Pragma("unroll") \
        for (int q = 0; q < 4; q++) { \
            float va = wv_[g * 8 + q * 2], vb = wv_[g * 8 + q * 2 + 1]; \
            bf16 ha = __float2bfloat16(va), hb = __float2bfloat16(vb); \
            hp_[q] = pack2(ha, hb); \
            lp_[q] = pack2(__float2bfloat16(va - __bfloat162float(ha)), \
                           __float2bfloat16(vb - __bfloat162float(hb))); \
        } \
        uint32_t off_ = SW128(rowoff + (g << 4)); \
        *(uint4*)(dst_ + off_) = make_uint4(hp_[0], hp_[1], hp_[2], hp_[3]); \
        *(uint4*)(dst_ + ASZ + off_) = make_uint4(lp_[0], lp_[1], lp_[2], lp_[3]); \
    } } while (0)

    float acc[MT][NT][4];
#pragma unroll
    for (int i = 0; i < MT; i++)
#pragma unroll
        for (int j = 0; j < NT; j++)
#pragma unroll
            for (int v = 0; v < 4; v++) acc[i][j][v] = 0.f;

    const int rsel = lane & 15, csel = lane >> 4;
    const int nch = M >> 6;
    STAGE_B(0, 0);
    BUILD_A(0, 0);
    for (int kc = 0; kc < nch; kc++) {
        if (kc + 1 < nch) { STAGE_B(kc + 1, (kc + 1) & 1); cpwait<1>(); }
        else cpwait<0>();
        __syncthreads();
        const uint32_t aH = sbase + (kc & 1) * STG;
        const uint32_t aL = aH + ASZ;
        const uint32_t bH = aH + ABY;
        const uint32_t bL = bH + BSZ;
#pragma unroll
        for (int ks = 0; ks < 4; ks++) {
            uint32_t ah[MT][4], al[MT][4], bh[NT][2], bl[NT][2];
#pragma unroll
            for (int mt = 0; mt < MT; mt++) {
                int row = wm * TMW + mt * 16 + rsel;
                uint32_t off = SW128((row << 7) + ((ks * 2 + csel) << 4));
                ldsm4(ah[mt][0], ah[mt][1], ah[mt][2], ah[mt][3], aH + off);
                ldsm4(al[mt][0], al[mt][1], al[mt][2], al[mt][3], aL + off);
            }
#pragma unroll
            for (int np = 0; np < NT / 2; np++) {
                int nr = wn * (TN / WN) + np * 16 + rsel;
                uint32_t off = SW128((nr << 7) + ((ks * 2 + csel) << 4));
                uint32_t r0, r1, r2, r3;
                ldsm4(r0, r1, r2, r3, bH + off);
                bh[2*np][0] = r0; bh[2*np+1][0] = r1; bh[2*np][1] = r2; bh[2*np+1][1] = r3;
                ldsm4(r0, r1, r2, r3, bL + off);
                bl[2*np][0] = r0; bl[2*np+1][0] = r1; bl[2*np][1] = r2; bl[2*np+1][1] = r3;
            }
#pragma unroll
            for (int mt = 0; mt < MT; mt++)
#pragma unroll
                for (int nt = 0; nt < NT; nt++) {
                    mma_bf16(acc[mt][nt], ah[mt], bh[nt]);
                    mma_bf16(acc[mt][nt], ah[mt], bl[nt]);
                    mma_bf16(acc[mt][nt], al[mt], bh[nt]);
                }
        }
        __syncthreads();
        if (kc + 1 < nch) BUILD_A(kc + 1, (kc + 1) & 1);
    }
    // epilogue: elu + split bf16 into concat buffer
    bf16* Dzh = Dh + (size_t)b * N * 1024 + (z & 7) * 64;
    bf16* Dzl = Dl + (size_t)b * N * 1024 + (z & 7) * 64;
#pragma unroll
    for (int mt = 0; mt < MT; mt++) {
        int row = n0 + wm * TMW + mt * 16 + (lane >> 2);
#pragma unroll
        for (int nt = 0; nt < NT; nt++) {
            int col = wn * (TN / WN) + nt * 8 + ((lane & 3) << 1);
            float v0 = acc[mt][nt][0], v1 = acc[mt][nt][1];
            float v2 = acc[mt][nt][2], v3 = acc[mt][nt][3];
            v0 = v0 > 0.f ? v0 : expm1f(v0);
            v1 = v1 > 0.f ? v1 : expm1f(v1);
            v2 = v2 > 0.f ? v2 : expm1f(v2);
            v3 = v3 > 0.f ? v3 : expm1f(v3);
            bf16 h0 = __float2bfloat16(v0), h1 = __float2bfloat16(v1);
            bf16 h2 = __float2bfloat16(v2), h3 = __float2bfloat16(v3);
            *(uint32_t*)&Dzh[(size_t)row * 1024 + col] = pack2(h0, h1);
            *(uint32_t*)&Dzh[(size_t)(row + 8) * 1024 + col] = pack2(h2, h3);
            *(uint32_t*)&Dzl[(size_t)row * 1024 + col] =
                pack2(__float2bfloat16(v0 - __bfloat162float(h0)),
                      __float2bfloat16(v1 - __bfloat162float(h1)));
            *(uint32_t*)&Dzl[(size_t)(row + 8) * 1024 + col] =
                pack2(__float2bfloat16(v2 - __bfloat162float(h2)),
                      __float2bfloat16(v3 - __bfloat162float(h3)));
        }
    }
#undef STAGE_B
#undef BUILD_A
}

// ---------------- prep / pointwise kernels ----------------
__global__ void prep_fusW(const float* W, const float* U, const float* Wf, const float* Uf) {
    int i = blockIdx.x * 256 + threadIdx.x;
    int zi = blockIdx.y;
    if (i >= 1024 * 1024) return;
    int n = i >> 10, k = i & 1023;
    size_t base = (size_t)zi * 512 * 512;
    float v;
    if (n < 512) v = (k < 512) ? W[base + (size_t)k*512 + n] : U[base + (size_t)(k-512)*512 + n];
    else         v = (k < 512) ? Wf[base + (size_t)k*512 + (n-512)] : Uf[base + (size_t)(k-512)*512 + (n-512)];
    bf16 h = __float2bfloat16(v);
    g_fWh[(size_t)zi * 1048576 + i] = h;
    g_fWl[(size_t)zi * 1048576 + i] = __float2bfloat16(v - __bfloat162float(h));
}
__global__ void prep_attW(const float* W, int slot) {
    int i = blockIdx.x * 256 + threadIdx.x;
    if (i >= 512 * 512) return;
    int n = i >> 9, k = i & 511;
    float v = W[((size_t)((n >> 6) * 512 + k)) * 64 + (n & 63)];
    bf16 h = __float2bfloat16(v);
    g_aWh[(size_t)slot * 262144 + i] = h;
    g_aWl[(size_t)slot * 262144 + i] = __float2bfloat16(v - __bfloat162float(h));
}
__global__ void prep_adj_cg(const int* adj) {
    int i = blockIdx.x * 256 + threadIdx.x; int b = blockIdx.y;
    if (i >= NG * NC) return;
    int gi = i >> 10, c = i & 1023;
    int a = adj[(size_t)b * NG * NC + i];
    unsigned char u = (a > 0);
    g_gc[(size_t)b * NG * NC + i] = u;
    size_t t = (size_t)b * NG * NC + (size_t)c * NG + gi;
    g_cg[t] = u;
    g_adjTb[t] = __float2bfloat16((float)a);
}
__global__ void prep_adj_gq(const int* adj) {
    int i = blockIdx.x * 256 + threadIdx.x; int b = blockIdx.y;
    if (i >= NG * NQ) return;
    int gi = i >> 8, q = i & 255;
    unsigned char u = (adj[(size_t)b * NG * NQ + i] > 0);
    g_gq[(size_t)b * NG * NQ + i] = u;
    g_qg[(size_t)b * NQ * NG + (size_t)q * NG + gi] = u;
}
__global__ void split_k(const float* __restrict__ src, bf16* dh, bf16* dl,
                        int total, int ostride, int coff) {
    int i = blockIdx.x * 256 + threadIdx.x;
    if (i >= total) return;
    int m = i >> 9, f = i & 511;
    float v = src[i];
    bf16 h = __float2bfloat16(v);
    size_t o = (size_t)m * ostride + coff + f;
    dh[o] = h; dl[o] = __float2bfloat16(v - __bfloat162float(h));
}
__global__ void tsplit_k(const float* __restrict__ src) {
    int i = blockIdx.x * 256 + threadIdx.x; int b = blockIdx.y;
    if (i >= NF * NG) return;
    int f = i >> 10, gi = i & 1023;
    float v = src[((size_t)b * NG + gi) * NF + f];
    bf16 h = __float2bfloat16(v);
    size_t o = (size_t)b * NF * NG + i;
    g_Gth[o] = h; g_Gtl[o] = __float2bfloat16(v - __bfloat162float(h));
}
__global__ void scoresE(const float* __restrict__ P, const float* __restrict__ a,
                        float* s, float* Ep, float* En, int Nt) {
    int i = blockIdx.x * 256 + threadIdx.x;
    if (i >= B_ * NH * Nt) return;
    int n = i % Nt, bh = i / Nt, h = bh & 7, b = bh >> 3;
    const float* row = P + ((size_t)b * Nt + n) * NF + h * HD;
    const float* av = a + h * HD;
    float acc = 0.f;
#pragma unroll
    for (int d = 0; d < 64; d++) acc += row[d] * av[d];
    s[i] = acc; Ep[i] = expf(acc); En[i] = expf(0.2f * acc);
}
__global__ void colsum_k(const unsigned char* __restrict__ adjmn,
                         const float* __restrict__ s1, const float* __restrict__ Ep1,
                         const float* __restrict__ En1,
                         const float* __restrict__ Ep2, const float* __restrict__ En2,
                         const float* __restrict__ s2, float* icS, int N, int M) {
    int b = blockIdx.y;
    int w = threadIdx.x >> 5, lane = threadIdx.x & 31;
    int m = blockIdx.x * 8 + w;
    if (m >= M) return;
    const unsigned char* arow = adjmn + ((size_t)b * M + m) * N;
    float s2v[8], Sp[8] = {}, Sn[8] = {};
#pragma unroll
    for (int h = 0; h < 8; h++) s2v[h] = s2[((size_t)(b * 8 + h)) * M + m];
    for (int n = lane; n < N; n += 32) {
        if (!arow[n]) continue;
#pragma unroll
        for (int h = 0; h < 8; h++) {
            size_t o = ((size_t)(b * 8 + h)) * N + n;
            if (s1[o] + s2v[h] > 0.f) Sp[h] += Ep1[o]; else Sn[h] += En1[o];
        }
    }
#pragma unroll
    for (int h = 0; h < 8; h++) {
        float p = Sp[h], q = Sn[h];
        for (int d = 16; d; d >>= 1) { p += __shfl_xor_sync(~0u, p, d); q += __shfl_xor_sync(~0u, q, d); }
        if (lane == 0) {
            size_t o = ((size_t)(b * 8 + h)) * M + m;
            icS[o] = 1.f / (Ep2[o] * p + En2[o] * q);
        }
    }
}
__global__ void vtprep_k(const float* __restrict__ Pk, const float* __restrict__ icS, int M) {
    int z = blockIdx.z, b = z >> 3, h = z & 7;
    int i = blockIdx.x * 256 + threadIdx.x;
    if (i >= 64 * M) return;
    int d = i / M, m = i % M;
    float v = Pk[((size_t)b * M + m) * NF + h * 64 + d] * icS[(size_t)z * M + m];
    bf16 hh = __float2bfloat16(v);
    size_t o = (size_t)z * 64 * M + i;
    g_Vth[o] = hh; g_Vtl[o] = __float2bfloat16(v - __bfloat162float(hh));
}
__global__ void fuse_ew(const float* __restrict__ a, const float* __restrict__ T12,
                        float* __restrict__ out, int total) {
    int i = blockIdx.x * 256 + threadIdx.x;
    if (i >= total) return;
    int m = i >> 9, f = i & 511;
    float t1 = T12[(size_t)m * 1024 + f], t2 = T12[(size_t)m * 1024 + 512 + f];
    float g = 1.f / (1.f + expf(-t2));
    out[i] = g * t1 + (1.f - g) * a[i];
}

// ---------------- host ----------------
template<typename T> static T* sa(const void* s) { void* p = nullptr; cudaGetSymbolAddress(&p, s); return (T*)p; }

struct Ctx {
    bf16 *fWh, *fWl, *aWh, *aWl, *adjTb, *Gth, *Gtl, *cath, *catl, *Axh, *Axl, *Vth, *Vtl;
    unsigned char *cg, *gc, *gq, *qg;
    float *Pq, *Pk, *T12, *G1, *Ga, *Ca, *Qa;
    float *s1, *Ep1, *En1, *s2, *Ep2, *En2, *icS;
};

static void run_fusion(Ctx& X, int l, int idx, const float* a, float* out, int Mrows) {
    // cat col 512.. already holds the b-part (adjT GEMM or attn_av2 output)
    int tot = Mrows * 512;
    split_k<<<(tot + 255) / 256, 256>>>(a, X.cath, X.catl, tot, 1024, 0);
    const bf16* wh = X.fWh + (size_t)(l * 4 + idx) * 1048576;
    const bf16* wl = X.fWl + (size_t)(l * 4 + idx) * 1048576;
    gemm_mm<3, 128, 0><<<dim3(8, Mrows / 128, 1), 256, 131072>>>(
        X.cath, X.catl, wh, wl, X.T12, nullptr, nullptr, 1024, 1024, 1024, 1024, 0, 0, 0);
    fuse_ew<<<(tot + 255) / 256, 256>>>(a, X.T12, out, tot);
}

static void run_attn(Ctx& X, int l, int which, const float* q, const float* kv,
                     int Nn, int Mkv, const unsigned char* adj_mn, const unsigned char* adj_nm,
                     const float* a1, const float* a2) {
    int slot = l * 3 + which;
    const bf16* wh = X.aWh + (size_t)slot * 262144;
    const bf16* wl = X.aWl + (size_t)slot * 262144;
    int tq = B_ * Nn * 512, tk = B_ * Mkv * 512;
    split_k<<<(tq + 255) / 256, 256>>>(q, X.Axh, X.Axl, tq, 512, 0);
    gemm_mm<3, 128, 0><<<dim3(4, B_ * Nn / 128, 1), 256, 131072>>>(
        X.Axh, X.Axl, wh, wl, X.Pq, nullptr, nullptr, 512, 512, 512, 512, 0, 0, 0);
    split_k<<<(tk + 255) / 256, 256>>>(kv, X.Axh, X.Axl, tk, 512, 0);
    gemm_mm<3, 128, 0><<<dim3(4, B_ * Mkv / 128, 1), 256, 131072>>>(
        X.Axh, X.Axl, wh, wl, X.Pk, nullptr, nullptr, 512, 512, 512, 512, 0, 0, 0);
    scoresE<<<(B_ * NH * Nn + 255) / 256, 256>>>(X.Pq, a1 + l * 512, X.s1, X.Ep1, X.En1, Nn);
    scoresE<<<(B_ * NH * Mkv + 255) / 256, 256>>>(X.Pk, a2 + l * 512, X.s2, X.Ep2, X.En2, Mkv);
    colsum_k<<<dim3((Mkv + 7) / 8, B_), 256>>>(adj_mn, X.s1, X.Ep1, X.En1, X.Ep2, X.En2, X.s2, X.icS, Nn, Mkv);
    vtprep_k<<<dim3((64 * Mkv + 255) / 256, 1, 32), 256>>>(X.Pk, X.icS, Mkv);
    attn_av2<<<dim3(1, Nn / 128, 32), 256, 98304>>>(
        adj_nm, X.s1, X.Ep1, X.En1, X.s2, X.Ep2, X.En2,
        X.Vth, X.Vtl, X.cath + 512, X.catl + 512, Nn, Mkv);
}

static void run_layer(Ctx& X, int l, const float* G, const float* C, const float* Q,
                      float* Gout, float* Cout, float* Qout,
                      const float* c2ga1, const float* c2ga2,
                      const float* g2qa1, const float* g2qa2,
                      const float* q2ga1, const float* q2ga2) {
    // gloss_same = adj^T @ gloss -> split bf16 directly into cat col 512
    tsplit_k<<<dim3((NF * NG) / 256, B_), 256>>>(G);
    gemm_mm<2, 128, 2><<<dim3(4, 8, B_), 256, 98304>>>(
        X.adjTb, X.adjTb, X.Gth, X.Gtl, nullptr, X.cath + 512, X.catl + 512,
        1024, 1024, 1024, 1024, (long)NG * NC, (long)NF * NG, (long)NC * 1024);
    run_fusion(X, l, 0, C, Cout, B_ * NC);                              // clip_new
    run_attn(X, l, 0, G, C, NG, NC, X.cg, X.gc, c2ga1, c2ga2);          // clip_agg -> cat512
    run_fusion(X, l, 1, G, X.G1, B_ * NG);                              // gloss_1
    run_attn(X, l, 1, Q, G, NQ, NG, X.gq, X.qg, g2qa1, g2qa2);          // gloss_agg -> cat512
    run_fusion(X, l, 2, Q, Qout, B_ * NQ);                              // question_new
    run_attn(X, l, 2, G, Q, NG, NQ, X.qg, X.gq, q2ga1, q2ga2);          // question_agg -> cat512
    run_fusion(X, l, 3, X.G1, Gout, B_ * NG);                           // gloss_new
}

extern "C" void kernel_launch(void* const* d_in, const int* in_sizes, int n_in,
                              void* d_out, int out_size) {
    (void)in_sizes; (void)n_in; (void)out_size;
    Ctx X;
    X.fWh = sa<bf16>(g_fWh); X.fWl = sa<bf16>(g_fWl);
    X.aWh = sa<bf16>(g_aWh); X.aWl = sa<bf16>(g_aWl);
    X.adjTb = sa<bf16>(g_adjTb);
    X.Gth = sa<bf16>(g_Gth); X.Gtl = sa<bf16>(g_Gtl);
    X.cath = sa<bf16>(g_cath); X.catl = sa<bf16>(g_catl);
    X.Axh = sa<bf16>(g_Axh); X.Axl = sa<bf16>(g_Axl);
    X.Vth = sa<bf16>(g_Vth); X.Vtl = sa<bf16>(g_Vtl);
    X.cg = sa<unsigned char>(g_cg); X.gc = sa<unsigned char>(g_gc);
    X.gq = sa<unsigned char>(g_gq); X.qg = sa<unsigned char>(g_qg);
    X.Pq = sa<float>(g_Pq); X.Pk = sa<float>(g_Pk);
    X.T12 = sa<float>(g_T12); X.G1 = sa<float>(g_G1);
    X.Ga = sa<float>(g_Ga); X.Ca = sa<float>(g_Ca); X.Qa = sa<float>(g_Qa);
    X.s1 = sa<float>(g_s1); X.Ep1 = sa<float>(g_Ep1); X.En1 = sa<float>(g_En1);
    X.s2 = sa<float>(g_s2); X.Ep2 = sa<float>(g_Ep2); X.En2 = sa<float>(g_En2);
    X.icS = sa<float>(g_icS);

    cudaFuncSetAttribute(gemm_mm<3,128,0>, cudaFuncAttributeMaxDynamicSharedMemorySize, 131072);
    cudaFuncSetAttribute(gemm_mm<2,128,2>, cudaFuncAttributeMaxDynamicSharedMemorySize, 98304);
    cudaFuncSetAttribute(attn_av2, cudaFuncAttributeMaxDynamicSharedMemorySize, 98304);

    const float* gloss    = (const float*)d_in[0];
    const float* clip     = (const float*)d_in[1];
    const float* question = (const float*)d_in[2];
    const int*   g2c      = (const int*)d_in[3];
    const int*   g2q      = (const int*)d_in[4];
    const float* c2gW  = (const float*)d_in[5];
    const float* c2ga1 = (const float*)d_in[6];
    const float* c2ga2 = (const float*)d_in[7];
    const float* g2qW  = (const float*)d_in[8];
    const float* g2qa1 = (const float*)d_in[9];
    const float* g2qa2 = (const float*)d_in[10];
    const float* q2gW  = (const float*)d_in[11];
    const float* q2ga1 = (const float*)d_in[12];
    const float* q2ga2 = (const float*)d_in[13];
    const float* fusW  = (const float*)d_in[14];
    const float* fusU  = (const float*)d_in[15];
    const float* fusWf = (const float*)d_in[16];
    const float* fusUf = (const float*)d_in[17];

    prep_fusW<<<dim3(4096, 8), 256>>>(fusW, fusU, fusWf, fusUf);
    const size_t AW = (size_t)NH * NF * HD;
    for (int l = 0; l < 2; l++) {
        prep_attW<<<1024, 256>>>(c2gW + l * AW, l * 3 + 0);
        prep_attW<<<1024, 256>>>(g2qW + l * AW, l * 3 + 1);
        prep_attW<<<1024, 256>>>(q2gW + l * AW, l * 3 + 2);
    }
    prep_adj_cg<<<dim3(4096, B_), 256>>>(g2c);
    prep_adj_gq<<<dim3(1024, B_), 256>>>(g2q);

    float* out = (float*)d_out;
    float* outG = out;
    float* outC = out + (size_t)B_ * NG * NF;
    float* outQ = outC + (size_t)B_ * NC * NF;

    run_layer(X, 0, gloss, clip, question, X.Ga, X.Ca, X.Qa,
              c2ga1, c2ga2, g2qa1, g2qa2, q2ga1, q2ga2);
    run_layer(X, 1, X.Ga, X.Ca, X.Qa, outG, outC, outQ,
              c2ga1, c2ga2, g2qa1, g2qa2, q2ga1, q2ga2);
}